// round 17
// baseline (speedup 1.0000x reference)
#include <cuda_runtime.h>
#include <math.h>

#define BB 2
#define DD 64
#define HH 96
#define WW 96
#define VOL (DD*HH*WW)          // 589824
#define NVOX (BB*VOL)           // 1179648
#define HWSZ (HH*WW)            // 9216
#define NPLANE (BB*DD)          // 128
#define HT 24                   // fused kernel h-tile (4 per plane)
#define WT3 16                  // pass3 w-tile
#define CLAMP 25.0f

#define NBLKBC (NPLANE*4)       // 512 fused blocks
#define NBLK3 (BB*HH*(WW/WT3))  // 1152 pass3 blocks

// Scratch (device globals: allocation-free per harness rules)
__device__ float g_x[NVOX];               // packed bp-bn after W+H transform (clamped 25)
__device__ volatile float g_pn[NBLK3];
__device__ volatile float g_pd[NBLK3];
__device__ unsigned g_count;              // zero-init; last block resets -> deterministic

// Windowed nearest-set-bit distance: 96-bit local window {m0,m1,m2} covering
// [seg*32-32, seg*32+64); voxel at bit wl of m1. Only d<=5 matters (clamp).
__device__ __forceinline__ int win_dist(unsigned m0, unsigned m1, unsigned m2, int wl) {
    unsigned long long U = (unsigned long long)m1 | ((unsigned long long)m2 << 32);
    unsigned long long D = (unsigned long long)m0 | ((unsigned long long)m1 << 32);
    unsigned long long a = U >> wl;           // bit0 = self, upward
    unsigned long long b = D << (31 - wl);    // MSB = self, downward
    int up = a ? (__ffsll((long long)a) - 1) : 64;
    int dn = b ? __clzll((long long)b) : 64;
    return (up < dn) ? up : dn;
}

// Fused: ballot mask build + pass1 (clamped W bit-scan, per-segment windows)
// + pass2 (k=1..4 branch-free H stencil). Block = (plane, full-W h-tile 24).
// (Unchanged from round 16 -- measured good.)
__global__ __launch_bounds__(256) void k_passBC(const float* __restrict__ tgt) {
    __shared__ unsigned sm[32][3];      // rows h0-4..h0+27, 3 segments each
    __shared__ float s1p[32 * WW];      // linear [row*96 + w]
    __shared__ float s1n[32 * WW];

    int ht = blockIdx.x & 3;
    int bd = blockIdx.x >> 2;
    int base = bd * HWSZ;
    int h0 = ht * HT;
    int tid = threadIdx.x;
    int lane = tid & 31;
    int warp = tid >> 5;                // 0..7

    // Ballot masks: 32 rows x 3 segs = 96 warp-tasks, 12 per warp.
    #pragma unroll
    for (int t = warp; t < 96; t += 8) {
        int r = t / 3;
        int s = t - r * 3;
        int hr = h0 - 4 + r;
        float v = (hr >= 0 && hr < HH) ? tgt[base + hr * WW + s * 32 + lane] : 0.0f;
        unsigned m = __ballot_sync(0xFFFFFFFFu, v > 0.5f);
        if (lane == 0) sm[r][s] = m;
    }
    __syncthreads();

    // pass1: clamped W-distance via per-segment windowed bit scan.
    #pragma unroll
    for (int r = warp; r < 32; r += 8) {
        int hr = h0 - 4 + r;
        if (hr < 0 || hr >= HH) {
            #pragma unroll
            for (int s = 0; s < 3; ++s) {
                s1p[r * WW + s * 32 + lane] = CLAMP;
                s1n[r * WW + s * 32 + lane] = CLAMP;
            }
        } else {
            unsigned q0 = sm[r][0], q1 = sm[r][1], q2 = sm[r][2];
            #pragma unroll
            for (int s = 0; s < 3; ++s) {
                unsigned m0 = (s > 0) ? ((s == 1) ? q0 : q1) : 0u;
                unsigned m1 = (s == 0) ? q0 : ((s == 1) ? q1 : q2);
                unsigned m2 = (s < 2) ? ((s == 0) ? q1 : q2) : 0u;
                unsigned val0 = (s > 0) ? 0xFFFFFFFFu : 0u;
                unsigned val2 = (s < 2) ? 0xFFFFFFFFu : 0u;
                int dn = win_dist(m0, m1, m2, lane);                    // nearest 1
                int dp = win_dist(val0 & ~m0, ~m1, val2 & ~m2, lane);   // nearest 0
                s1p[r * WW + s * 32 + lane] = (dp >= 5) ? CLAMP : (float)(dp * dp);
                s1n[r * WW + s * 32 + lane] = (dn >= 5) ? CLAMP : (float)(dn * dn);
            }
        }
    }
    __syncthreads();

    // pass2 along H: fixed k=1..4 stencil (exact under clamp), 9 voxels/thread.
    #pragma unroll
    for (int v = tid; v < HT * WW; v += 256) {
        int i = v / WW;
        int c = v - i * WW;
        int rr = (i + 4) * WW + c;
        float bp = s1p[rr];
        float bn = s1n[rr];
        #pragma unroll
        for (int k = 1; k <= 4; ++k) {
            float k2 = (float)(k * k);
            bp = fminf(bp, s1p[rr - k * WW] + k2);
            bp = fminf(bp, s1p[rr + k * WW] + k2);
            bn = fminf(bn, s1n[rr - k * WW] + k2);
            bn = fminf(bn, s1n[rr + k * WW] + k2);
        }
        g_x[base + (h0 + i) * WW + c] = bp - bn;   // exactly one side is 0
    }
}

// Pass3: single-sided k=1..4 D-stencil on raw packed smem (no decode, half
// the ALU), fused loss epilogue (group-4 log) + grid-final reduction.
__global__ __launch_bounds__(256) void k_pass3(const float* __restrict__ pred,
                                               float* __restrict__ out) {
    __shared__ float sfx[DD][17];       // raw packed x; stride 17 conflict-free
    __shared__ float rnm[8], rdm[8];
    __shared__ int s_last;

    int wt = blockIdx.x % (WW / WT3);       // 0..5
    int bh = blockIdx.x / (WW / WT3);
    int b = bh / HH;
    int h = bh % HH;
    int base = b * VOL + h * WW + wt * WT3;
    int tid = threadIdx.x;
    int w = tid & 15;
    int c0 = tid >> 4;                      // 0..15
    int i0 = c0 * 4;                        // 4 consecutive i per thread

    // Issue pred LDGs first (latency hidden behind smem fill + stencil).
    float pv[4];
    #pragma unroll
    for (int j = 0; j < 4; ++j) pv[j] = pred[base + (i0 + j) * HWSZ + w];

    // Fill smem with raw packed values (4 STS/thread, coalesced).
    #pragma unroll
    for (int r = tid; r < DD * WT3; r += 256) {
        int d = r >> 4, ww_ = r & 15;
        sfx[d][ww_] = g_x[base + d * HWSZ + ww_];
    }
    __syncthreads();

    // Stage 12-row window; out-of-range rows -> 0 (contribution k^2: can only
    // pull m below the weight-1 threshold; sign/t unaffected -> output-equal).
    float x[12];
    #pragma unroll
    for (int j = 0; j < 12; ++j) {
        int d = i0 + j - 4;
        x[j] = ((unsigned)d < (unsigned)DD) ? sfx[d][w] : 0.0f;
    }

    float mArr[4], pcArr[4];
    #pragma unroll
    for (int j = 0; j < 4; ++j) {
        float xc = x[j + 4];
        float sgn = (xc > 0.0f) ? 1.0f : -1.0f;   // s: which side is nonzero
        float m = fabsf(xc);
        #pragma unroll
        for (int k = 1; k <= 4; ++k) {
            float k2 = (float)(k * k);
            // fmax(s*x_j,0)+k2 == fmax(s*x_j + k2, k2), exact.
            m = fminf(m, fmaxf(fmaf(x[j + 4 - k], sgn, k2), k2));
            m = fminf(m, fmaxf(fmaf(x[j + 4 + k], sgn, k2), k2));
        }
        mArr[j] = m;
        pcArr[j] = (xc > 0.0f) ? pv[j] : (1.0f - pv[j]);   // t==1 <=> x_c>0
    }

    float accn, accd;
    bool fast = true;
    float prod = 1.0f;
    #pragma unroll
    for (int j = 0; j < 4; ++j) {
        if (mArr[j] > 9.0f) fast = false;
        prod *= pcArr[j];
    }
    if (fast && prod > 1e-30f) {
        accn = -__logf(prod);      // all w==1: sum(-log pc) == -log(prod)
        accd = 4.0f;
    } else {
        accn = 0.0f; accd = 0.0f;
        #pragma unroll
        for (int j = 0; j < 4; ++j) {
            float m = mArr[j];
            float wgt;
            if (m <= 9.0f)       wgt = 1.0f;
            else if (m >= 25.0f) wgt = 0.0f;
            else                 wgt = 1.0f - (sqrtf(m) - 3.0f) * 0.5f;
            float bce = -fmaxf(__logf(pcArr[j]), -100.0f);
            accn += bce * wgt;
            accd += wgt;
        }
    }

    #pragma unroll
    for (int off = 16; off > 0; off >>= 1) {
        accn += __shfl_down_sync(0xFFFFFFFFu, accn, off);
        accd += __shfl_down_sync(0xFFFFFFFFu, accd, off);
    }
    int warp = tid >> 5, lane = tid & 31;
    if (lane == 0) { rnm[warp] = accn; rdm[warp] = accd; }
    __syncthreads();
    if (tid == 0) {
        float sn = 0.0f, sd = 0.0f;
        #pragma unroll
        for (int j = 0; j < 8; ++j) { sn += rnm[j]; sd += rdm[j]; }
        g_pn[blockIdx.x] = sn;
        g_pd[blockIdx.x] = sd;
        __threadfence();
        unsigned old = atomicAdd(&g_count, 1u);
        s_last = (old == NBLK3 - 1) ? 1 : 0;
    }
    __syncthreads();

    // Last block: reduce all 1152 partials -> scalar, reset counter.
    if (s_last) {
        __shared__ double wn[8], wd[8];
        const int PER_B = NBLK3 / BB;     // 576
        int rb = tid >> 7;                // 0..1 (batch)
        int j0 = tid & 127;
        double an = 0.0, ad = 0.0;
        #pragma unroll
        for (int j = j0; j < PER_B; j += 128) {
            an += (double)g_pn[rb * PER_B + j];
            ad += (double)g_pd[rb * PER_B + j];
        }
        #pragma unroll
        for (int off = 16; off > 0; off >>= 1) {
            an += __shfl_down_sync(0xFFFFFFFFu, an, off);
            ad += __shfl_down_sync(0xFFFFFFFFu, ad, off);
        }
        if (lane == 0) { wn[warp] = an; wd[warp] = ad; }
        __syncthreads();
        if (tid == 0) {
            double n0 = 0.0, dd0 = 0.0, n1 = 0.0, dd1 = 0.0;
            #pragma unroll
            for (int j = 0; j < 4; ++j) { n0 += wn[j]; dd0 += wd[j]; }
            #pragma unroll
            for (int j = 4; j < 8; ++j) { n1 += wn[j]; dd1 += wd[j]; }
            double acc = n0 / (dd0 + 1e-5) + n1 / (dd1 + 1e-5);
            out[0] = (float)(acc / (double)BB);
            g_count = 0;   // reset for next graph replay
        }
    }
}

extern "C" void kernel_launch(void* const* d_in, const int* in_sizes, int n_in,
                              void* d_out, int out_size) {
    const float* pred = (const float*)d_in[0];
    const float* tgt  = (const float*)d_in[1];
    (void)in_sizes; (void)n_in; (void)out_size;

    k_passBC<<<NBLKBC, 256>>>(tgt);                 // 512 blocks (mask fused)
    k_pass3<<<NBLK3, 256>>>(pred, (float*)d_out);   // 1152 blocks
}